// round 10
// baseline (speedup 1.0000x reference)
#include <cuda_runtime.h>
#include <cuda_fp16.h>

#define Nn 100000
#define Ee 1600000
#define NB 391            // ceil(Nn/256) scan blocks

typedef unsigned long long u64;

// ---------------- scratch (device globals; allocation-free) ----------------
__device__ unsigned g_feat1h[Nn * 64]; // layer1 features as half2 [N][64 pairs]
__device__ float g_el1[Nn * 4];
__device__ float g_er1[Nn * 4];
__device__ float g_feat2[Nn * 16];    // layer2 projected features
__device__ float g_el2[Nn];
__device__ float g_er2[Nn];
// CSR by dst
__device__ int g_counts[Nn];
__device__ int g_offs[Nn];
__device__ int g_cursor[Nn];
__device__ int g_bsums[NB];
__device__ int g_csr_src[Ee];

__device__ __forceinline__ float leaky02(float x) {
    return x > 0.f ? x : 0.2f * x;
}

// packed f32x2 helpers (FFMA2 is PTX-only; ptxas never auto-fuses)
__device__ __forceinline__ u64 dup2(float v) {
    u64 d; asm("mov.b64 %0, {%1, %1};" : "=l"(d) : "f"(v)); return d;
}
__device__ __forceinline__ void fma2(u64& d, u64 a, u64 b) {
    asm("fma.rn.f32x2 %0, %1, %2, %0;" : "+l"(d) : "l"(a), "l"(b));
}
__device__ __forceinline__ void unpack2(float& lo, float& hi, u64 v) {
    asm("mov.b64 {%0, %1}, %2;" : "=f"(lo), "=f"(hi) : "l"(v));
}

// ---------------- init: zero CSR counts ------------------------------------
__global__ void init_kernel() {
    int i = blockIdx.x * blockDim.x + threadIdx.x;
    if (i < Nn) g_counts[i] = 0;
}

// ---------------- GEMM1 + el/er epilogue (f32x2 packed FMA) ----------------
// feat1 = x @ W1 (100000x128 @ 128x128); per-head el/er reduced in-warp
// from the fp32 accumulators; features stored as half2 for the gather phase.
__global__ void gemm1_kernel(const float* __restrict__ x, const float* __restrict__ W1,
                             const float* __restrict__ al1, const float* __restrict__ ar1) {
    __shared__ float xsT[128 * 36];
    int tid = threadIdx.x;
    int nblk = blockIdx.x * 32;

#pragma unroll
    for (int r = 0; r < 4; r++) {
        int fi = tid + r * 256;
        int i = fi >> 5;
        int kq = fi & 31;
        float4 v = *(const float4*)&x[(nblk + i) * 128 + kq * 4];
        xsT[(kq * 4 + 0) * 36 + i] = v.x;
        xsT[(kq * 4 + 1) * 36 + i] = v.y;
        xsT[(kq * 4 + 2) * 36 + i] = v.z;
        xsT[(kq * 4 + 3) * 36 + i] = v.w;
    }
    __syncthreads();

    int tx = tid & 31;      // lane; col group tx*4..tx*4+3
    int ty = tid >> 5;      // warp; node group ty*4..ty*4+3
    int n0 = ty * 4;
    // accP[g][b]: packed pair over nodes (n0+2g, n0+2g+1), column b
    u64 accP[2][4] = {};
    const float4* W4 = (const float4*)W1;

#pragma unroll 4
    for (int k = 0; k < 128; k++) {
        float4 xv = *(const float4*)&xsT[k * 36 + n0];  // warp-broadcast
        u64 a01, a23;
        asm("mov.b64 %0, {%1, %2};" : "=l"(a01) : "f"(xv.x), "f"(xv.y));
        asm("mov.b64 %0, {%1, %2};" : "=l"(a23) : "f"(xv.z), "f"(xv.w));
        float4 wv = __ldg(&W4[k * 32 + tx]);            // coalesced 512B row
        u64 w0 = dup2(wv.x), w1 = dup2(wv.y), w2 = dup2(wv.z), w3 = dup2(wv.w);
        fma2(accP[0][0], a01, w0); fma2(accP[0][1], a01, w1);
        fma2(accP[0][2], a01, w2); fma2(accP[0][3], a01, w3);
        fma2(accP[1][0], a23, w0); fma2(accP[1][1], a23, w1);
        fma2(accP[1][2], a23, w2); fma2(accP[1][3], a23, w3);
    }

    // unpack to per-node scalars (fp32)
    float acc[4][4];
#pragma unroll
    for (int g = 0; g < 2; g++)
#pragma unroll
        for (int b = 0; b < 4; b++)
            unpack2(acc[2 * g][b], acc[2 * g + 1][b], accP[g][b]);

    // store features as half2 pairs (256B per node)
#pragma unroll
    for (int a = 0; a < 4; a++) {
        __half2 h0 = __floats2half2_rn(acc[a][0], acc[a][1]);
        __half2 h1 = __floats2half2_rn(acc[a][2], acc[a][3]);
        uint2 st;
        st.x = *(unsigned*)&h0;
        st.y = *(unsigned*)&h1;
        *(uint2*)&g_feat1h[(nblk + n0 + a) * 64 + tx * 2] = st;
    }

    // epilogue: el/er from fp32 accumulators. head = tx>>3.
    float4 av = __ldg(&((const float4*)al1)[tx]);
    float4 rv = __ldg(&((const float4*)ar1)[tx]);
    int head = tx >> 3;
#pragma unroll
    for (int a = 0; a < 4; a++) {
        float el = acc[a][0] * av.x + acc[a][1] * av.y + acc[a][2] * av.z + acc[a][3] * av.w;
        float er = acc[a][0] * rv.x + acc[a][1] * rv.y + acc[a][2] * rv.z + acc[a][3] * rv.w;
        el += __shfl_xor_sync(0xffffffffu, el, 1);
        er += __shfl_xor_sync(0xffffffffu, er, 1);
        el += __shfl_xor_sync(0xffffffffu, el, 2);
        er += __shfl_xor_sync(0xffffffffu, er, 2);
        el += __shfl_xor_sync(0xffffffffu, el, 4);
        er += __shfl_xor_sync(0xffffffffu, er, 4);
        if ((tx & 7) == 0) {
            int n = nblk + n0 + a;
            g_el1[n * 4 + head] = el;
            g_er1[n * 4 + head] = er;
        }
    }
}

// ---------------- CSR build -------------------------------------------------
__global__ void hist_kernel(const int* __restrict__ dst) {
    int e = blockIdx.x * blockDim.x + threadIdx.x;
    if (e < Ee) atomicAdd(&g_counts[dst[e]], 1);
}

__global__ void scan_block_kernel() {
    __shared__ int sh[256];
    int t = threadIdx.x;
    int i = blockIdx.x * 256 + t;
    int v = (i < Nn) ? g_counts[i] : 0;
    sh[t] = v;
    __syncthreads();
    for (int off = 1; off < 256; off <<= 1) {
        int add = (t >= off) ? sh[t - off] : 0;
        __syncthreads();
        sh[t] += add;
        __syncthreads();
    }
    if (i < Nn) g_offs[i] = sh[t] - v;        // exclusive within block
    if (t == 255) g_bsums[blockIdx.x] = sh[t];
}

__global__ void scan_sums_kernel() {
    __shared__ int sh[512];
    int t = threadIdx.x;
    int v = (t < NB) ? g_bsums[t] : 0;
    sh[t] = v;
    __syncthreads();
    for (int off = 1; off < 512; off <<= 1) {
        int add = (t >= off) ? sh[t - off] : 0;
        __syncthreads();
        sh[t] += add;
        __syncthreads();
    }
    if (t < NB) g_bsums[t] = sh[t] - v;       // exclusive
}

__global__ void scan_add_kernel() {
    int i = blockIdx.x * 256 + threadIdx.x;
    if (i < Nn) {
        int o = g_offs[i] + g_bsums[i >> 8];
        g_offs[i] = o;
        g_cursor[i] = o;
    }
}

__global__ void fill_kernel(const int* __restrict__ src, const int* __restrict__ dst) {
    int e = blockIdx.x * blockDim.x + threadIdx.x;
    if (e < Ee) {
        int s = src[e];
        int p = atomicAdd(&g_cursor[dst[e]], 1);
        g_csr_src[p] = s;
    }
}

// ---------------- agg1: fused softmax+aggregate+mid (warp per dst node) ----
// Produces feat2, el2, er2 directly. Messages gathered as half2.
__global__ void agg1_kernel(const float* __restrict__ b1, const float* __restrict__ W2,
                            const float* __restrict__ al2, const float* __restrict__ ar2) {
    int n = (blockIdx.x * blockDim.x + threadIdx.x) >> 5;
    int lane = threadIdx.x & 31;
    if (n >= Nn) return;
    int head = lane >> 3;
    int start = g_offs[n];
    int end = start + g_counts[n];
    float er = g_er1[n * 4 + head];
    float denom = 0.f;
    float4 acc = make_float4(0.f, 0.f, 0.f, 0.f);

#pragma unroll 8
    for (int p = start; p < end; p++) {
        int s = __ldg(&g_csr_src[p]);               // warp-broadcast load
        float el = __ldg(&g_el1[s * 4 + head]);
        float ex = __expf(leaky02(el + er));
        denom += ex;
        uint2 raw = *(const uint2*)&g_feat1h[s * 64 + lane * 2];  // coalesced 256B
        float2 f0 = __half22float2(*(__half2*)&raw.x);
        float2 f1 = __half22float2(*(__half2*)&raw.y);
        acc.x = fmaf(ex, f0.x, acc.x);
        acc.y = fmaf(ex, f0.y, acc.y);
        acc.z = fmaf(ex, f1.x, acc.z);
        acc.w = fmaf(ex, f1.y, acc.w);
    }
    float inv = (denom > 0.f) ? __frcp_rn(denom) : 0.f;
    float4 bv = *(const float4*)&b1[lane * 4];
    float y[4] = {fmaf(acc.x, inv, bv.x), fmaf(acc.y, inv, bv.y),
                  fmaf(acc.z, inv, bv.z), fmaf(acc.w, inv, bv.w)};
    // mean over the 4 heads: lanes {L, L^8, L^16, L^24}
#pragma unroll
    for (int c = 0; c < 4; c++) {
        y[c] += __shfl_xor_sync(0xffffffffu, y[c], 8);
        y[c] += __shfl_xor_sync(0xffffffffu, y[c], 16);
    }
    float hv[4];
#pragma unroll
    for (int c = 0; c < 4; c++) hv[c] = fmaxf(0.25f * y[c], 0.f);
    // lane L holds hv for dims (L&7)*4..+3 (replicated across head groups)

    int d0 = (lane & 7) * 4;
    float p16[16] = {};
#pragma unroll
    for (int c = 0; c < 4; c++) {
        float h = hv[c];
        const float4* wrow = (const float4*)&W2[(d0 + c) * 16];
#pragma unroll
        for (int q = 0; q < 4; q++) {
            float4 w = __ldg(&wrow[q]);
            p16[q * 4 + 0] = fmaf(h, w.x, p16[q * 4 + 0]);
            p16[q * 4 + 1] = fmaf(h, w.y, p16[q * 4 + 1]);
            p16[q * 4 + 2] = fmaf(h, w.z, p16[q * 4 + 2]);
            p16[q * 4 + 3] = fmaf(h, w.w, p16[q * 4 + 3]);
        }
    }
    // reduce across the 8 lanes of each group
#pragma unroll
    for (int o = 1; o <= 4; o <<= 1)
#pragma unroll
        for (int j = 0; j < 16; j++)
            p16[j] += __shfl_xor_sync(0xffffffffu, p16[j], o);
    // every lane now holds full feat2[n][0..15]
    if (lane < 4) {
        float4 o4 = make_float4(p16[lane * 4], p16[lane * 4 + 1],
                                p16[lane * 4 + 2], p16[lane * 4 + 3]);
        *(float4*)&g_feat2[n * 16 + lane * 4] = o4;
    }
    if (lane == 0) {
        float el2 = 0.f, er2 = 0.f;
#pragma unroll
        for (int j = 0; j < 16; j++) {
            el2 = fmaf(p16[j], al2[j], el2);
            er2 = fmaf(p16[j], ar2[j], er2);
        }
        g_el2[n] = el2;
        g_er2[n] = er2;
    }
}

// ---------------- agg2: layer-2 softmax+aggregate (4 lanes per dst node) ---
__global__ void agg2_kernel(const float* __restrict__ b2, float* __restrict__ out) {
    int t = blockIdx.x * blockDim.x + threadIdx.x;
    int n = t >> 2;
    if (n >= Nn) return;
    int c = (t & 3) * 4;
    int start = g_offs[n];
    int end = start + g_counts[n];
    float er = g_er2[n];
    float denom = 0.f;
    float4 acc = make_float4(0.f, 0.f, 0.f, 0.f);
#pragma unroll 8
    for (int p = start; p < end; p++) {
        int s = __ldg(&g_csr_src[p]);
        float ex = __expf(leaky02(__ldg(&g_el2[s]) + er));
        denom += ex;
        float4 f = *(const float4*)&g_feat2[s * 16 + c];
        acc.x = fmaf(ex, f.x, acc.x);
        acc.y = fmaf(ex, f.y, acc.y);
        acc.z = fmaf(ex, f.z, acc.z);
        acc.w = fmaf(ex, f.w, acc.w);
    }
    float inv = (denom > 0.f) ? __frcp_rn(denom) : 0.f;
    float4 bv = *(const float4*)&b2[c];
    float4 o4 = make_float4(fmaf(acc.x, inv, bv.x), fmaf(acc.y, inv, bv.y),
                            fmaf(acc.z, inv, bv.z), fmaf(acc.w, inv, bv.w));
    *(float4*)&out[n * 16 + c] = o4;
}

// ---------------- launch ----------------------------------------------------
extern "C" void kernel_launch(void* const* d_in, const int* in_sizes, int n_in,
                              void* d_out, int out_size) {
    const float* x   = (const float*)d_in[0];
    const int*   src = (const int*)d_in[1];
    const int*   dst = (const int*)d_in[2];
    const float* W1  = (const float*)d_in[3];
    const float* al1 = (const float*)d_in[4];
    const float* ar1 = (const float*)d_in[5];
    const float* b1  = (const float*)d_in[6];
    const float* W2  = (const float*)d_in[7];
    const float* al2 = (const float*)d_in[8];
    const float* ar2 = (const float*)d_in[9];
    const float* b2  = (const float*)d_in[10];
    float* out = (float*)d_out;

    init_kernel<<<NB, 256>>>();
    hist_kernel<<<(Ee + 255) / 256, 256>>>(dst);
    scan_block_kernel<<<NB, 256>>>();
    gemm1_kernel<<<Nn / 32, 256>>>(x, W1, al1, ar1);   // 4th launch → profiled slot
    scan_sums_kernel<<<1, 512>>>();
    scan_add_kernel<<<NB, 256>>>();
    fill_kernel<<<(Ee + 255) / 256, 256>>>(src, dst);
    agg1_kernel<<<(Nn * 32 + 255) / 256, 256>>>(b1, W2, al2, ar2);
    agg2_kernel<<<(Nn * 4 + 255) / 256, 256>>>(b2, out);
}

// round 11
// speedup vs baseline: 1.0314x; 1.0314x over previous
#include <cuda_runtime.h>

#define Nn 100000
#define Ee 1600000
#define NB 391            // ceil(Nn/256) scan blocks
#define GB1 1563          // ceil(Nn/64) gemm1 blocks

typedef unsigned long long u64;

// ---------------- scratch (device globals; allocation-free) ----------------
__device__ float g_feat1[Nn * 128];   // layer1 projected features [N,4,32]
__device__ float g_el1[Nn * 4];
__device__ float g_er1[Nn * 4];
__device__ float g_feat2[Nn * 16];    // layer2 projected features
__device__ float g_el2[Nn];
__device__ float g_er2[Nn];
// CSR by dst
__device__ int g_counts[Nn];
__device__ int g_offs[Nn];
__device__ int g_cursor[Nn];
__device__ int g_bsums[NB];
__device__ int g_csr_src[Ee];

__device__ __forceinline__ float leaky02(float x) {
    return x > 0.f ? x : 0.2f * x;
}

// packed f32x2 helpers (FFMA2 is PTX-only; ptxas never auto-fuses)
__device__ __forceinline__ u64 dup2(float v) {
    u64 d; asm("mov.b64 %0, {%1, %1};" : "=l"(d) : "f"(v)); return d;
}
__device__ __forceinline__ u64 pack2(float lo, float hi) {
    u64 d; asm("mov.b64 %0, {%1, %2};" : "=l"(d) : "f"(lo), "f"(hi)); return d;
}
__device__ __forceinline__ void fma2(u64& d, u64 a, u64 b) {
    asm("fma.rn.f32x2 %0, %1, %2, %0;" : "+l"(d) : "l"(a), "l"(b));
}
__device__ __forceinline__ void unpack2(float& lo, float& hi, u64 v) {
    asm("mov.b64 {%0, %1}, %2;" : "=f"(lo), "=f"(hi) : "l"(v));
}

// ---------------- init: zero CSR counts ------------------------------------
__global__ void init_kernel() {
    int i = blockIdx.x * blockDim.x + threadIdx.x;
    if (i < Nn) g_counts[i] = 0;
}

// ---------------- GEMM1 + el/er epilogue (f32x2, 64-node tile) -------------
// feat1 = x @ W1 (100000x128 @ 128x128). Each block: 64 nodes; each thread:
// 8 nodes x 4 cols. One W LDG.128 per k feeds 16 FMA2s (halved L1 traffic).
__global__ void gemm1_kernel(const float* __restrict__ x, const float* __restrict__ W1,
                             const float* __restrict__ al1, const float* __restrict__ ar1) {
    __shared__ float xsT[128 * 68];   // [k][node], stride 68 keeps float4 align + skew
    int tid = threadIdx.x;
    int nblk = blockIdx.x * 64;

    // load 64 nodes x 128 k, transposed (guard the N tail)
#pragma unroll
    for (int r = 0; r < 8; r++) {
        int fi = tid + r * 256;          // float4 index within tile
        int i = fi >> 5;                 // node 0..63
        int kq = fi & 31;                // float4 index within row
        int n = nblk + i;
        float4 v = (n < Nn) ? *(const float4*)&x[n * 128 + kq * 4]
                            : make_float4(0.f, 0.f, 0.f, 0.f);
        xsT[(kq * 4 + 0) * 68 + i] = v.x;
        xsT[(kq * 4 + 1) * 68 + i] = v.y;
        xsT[(kq * 4 + 2) * 68 + i] = v.z;
        xsT[(kq * 4 + 3) * 68 + i] = v.w;
    }
    __syncthreads();

    int tx = tid & 31;      // lane; col group tx*4..tx*4+3
    int ty = tid >> 5;      // warp; node group ty*8..ty*8+7
    int n0 = ty * 8;
    // accP[g][b]: packed pair over nodes (n0+2g, n0+2g+1), column b
    u64 accP[4][4] = {};
    const float4* W4 = (const float4*)W1;

#pragma unroll 2
    for (int k = 0; k < 128; k++) {
        float4 xv0 = *(const float4*)&xsT[k * 68 + n0];      // nodes n0..n0+3
        float4 xv1 = *(const float4*)&xsT[k * 68 + n0 + 4];  // nodes n0+4..n0+7
        u64 a01 = pack2(xv0.x, xv0.y);
        u64 a23 = pack2(xv0.z, xv0.w);
        u64 a45 = pack2(xv1.x, xv1.y);
        u64 a67 = pack2(xv1.z, xv1.w);
        float4 wv = __ldg(&W4[k * 32 + tx]);                 // coalesced 512B row
        u64 w0 = dup2(wv.x), w1 = dup2(wv.y), w2 = dup2(wv.z), w3 = dup2(wv.w);
        fma2(accP[0][0], a01, w0); fma2(accP[0][1], a01, w1);
        fma2(accP[0][2], a01, w2); fma2(accP[0][3], a01, w3);
        fma2(accP[1][0], a23, w0); fma2(accP[1][1], a23, w1);
        fma2(accP[1][2], a23, w2); fma2(accP[1][3], a23, w3);
        fma2(accP[2][0], a45, w0); fma2(accP[2][1], a45, w1);
        fma2(accP[2][2], a45, w2); fma2(accP[2][3], a45, w3);
        fma2(accP[3][0], a67, w0); fma2(accP[3][1], a67, w1);
        fma2(accP[3][2], a67, w2); fma2(accP[3][3], a67, w3);
    }

    // unpack to per-node scalars
    float acc[8][4];
#pragma unroll
    for (int g = 0; g < 4; g++)
#pragma unroll
        for (int b = 0; b < 4; b++)
            unpack2(acc[2 * g][b], acc[2 * g + 1][b], accP[g][b]);

#pragma unroll
    for (int a = 0; a < 8; a++) {
        int n = nblk + n0 + a;
        if (n < Nn) {
            float4 o = make_float4(acc[a][0], acc[a][1], acc[a][2], acc[a][3]);
            *(float4*)&g_feat1[n * 128 + tx * 4] = o;
        }
    }

    // epilogue: el/er. col = tx*4+b, head = tx>>3; reduce over 8 lanes of head group.
    float4 av = __ldg(&((const float4*)al1)[tx]);
    float4 rv = __ldg(&((const float4*)ar1)[tx]);
    int head = tx >> 3;
#pragma unroll
    for (int a = 0; a < 8; a++) {
        float el = acc[a][0] * av.x + acc[a][1] * av.y + acc[a][2] * av.z + acc[a][3] * av.w;
        float er = acc[a][0] * rv.x + acc[a][1] * rv.y + acc[a][2] * rv.z + acc[a][3] * rv.w;
        el += __shfl_xor_sync(0xffffffffu, el, 1);
        er += __shfl_xor_sync(0xffffffffu, er, 1);
        el += __shfl_xor_sync(0xffffffffu, el, 2);
        er += __shfl_xor_sync(0xffffffffu, er, 2);
        el += __shfl_xor_sync(0xffffffffu, el, 4);
        er += __shfl_xor_sync(0xffffffffu, er, 4);
        int n = nblk + n0 + a;
        if ((tx & 7) == 0 && n < Nn) {
            g_el1[n * 4 + head] = el;
            g_er1[n * 4 + head] = er;
        }
    }
}

// ---------------- CSR build -------------------------------------------------
__global__ void hist_kernel(const int* __restrict__ dst) {
    int e = blockIdx.x * blockDim.x + threadIdx.x;
    if (e < Ee) atomicAdd(&g_counts[dst[e]], 1);
}

__global__ void scan_block_kernel() {
    __shared__ int sh[256];
    int t = threadIdx.x;
    int i = blockIdx.x * 256 + t;
    int v = (i < Nn) ? g_counts[i] : 0;
    sh[t] = v;
    __syncthreads();
    for (int off = 1; off < 256; off <<= 1) {
        int add = (t >= off) ? sh[t - off] : 0;
        __syncthreads();
        sh[t] += add;
        __syncthreads();
    }
    if (i < Nn) g_offs[i] = sh[t] - v;        // exclusive within block
    if (t == 255) g_bsums[blockIdx.x] = sh[t];
}

__global__ void scan_sums_kernel() {
    __shared__ int sh[512];
    int t = threadIdx.x;
    int v = (t < NB) ? g_bsums[t] : 0;
    sh[t] = v;
    __syncthreads();
    for (int off = 1; off < 512; off <<= 1) {
        int add = (t >= off) ? sh[t - off] : 0;
        __syncthreads();
        sh[t] += add;
        __syncthreads();
    }
    if (t < NB) g_bsums[t] = sh[t] - v;       // exclusive
}

__global__ void scan_add_kernel() {
    int i = blockIdx.x * 256 + threadIdx.x;
    if (i < Nn) {
        int o = g_offs[i] + g_bsums[i >> 8];
        g_offs[i] = o;
        g_cursor[i] = o;
    }
}

__global__ void fill_kernel(const int* __restrict__ src, const int* __restrict__ dst) {
    int e = blockIdx.x * blockDim.x + threadIdx.x;
    if (e < Ee) {
        int s = src[e];
        int p = atomicAdd(&g_cursor[dst[e]], 1);
        g_csr_src[p] = s;
    }
}

// ---------------- agg1: fused softmax+aggregate+mid (warp per dst node) ----
// Produces feat2, el2, er2 directly.
__global__ void agg1_kernel(const float* __restrict__ b1, const float* __restrict__ W2,
                            const float* __restrict__ al2, const float* __restrict__ ar2) {
    int n = (blockIdx.x * blockDim.x + threadIdx.x) >> 5;
    int lane = threadIdx.x & 31;
    if (n >= Nn) return;
    int head = lane >> 3;
    int start = g_offs[n];
    int end = start + g_counts[n];
    float er = g_er1[n * 4 + head];
    float denom = 0.f;
    float4 acc = make_float4(0.f, 0.f, 0.f, 0.f);

#pragma unroll 8
    for (int p = start; p < end; p++) {
        int s = __ldg(&g_csr_src[p]);               // warp-broadcast load
        float el = __ldg(&g_el1[s * 4 + head]);
        float ex = __expf(leaky02(el + er));
        denom += ex;
        float4 f = *(const float4*)&g_feat1[s * 128 + lane * 4];  // coalesced 512B
        acc.x = fmaf(ex, f.x, acc.x);
        acc.y = fmaf(ex, f.y, acc.y);
        acc.z = fmaf(ex, f.z, acc.z);
        acc.w = fmaf(ex, f.w, acc.w);
    }
    float inv = (denom > 0.f) ? __frcp_rn(denom) : 0.f;
    float4 bv = *(const float4*)&b1[lane * 4];
    float y[4] = {fmaf(acc.x, inv, bv.x), fmaf(acc.y, inv, bv.y),
                  fmaf(acc.z, inv, bv.z), fmaf(acc.w, inv, bv.w)};
    // mean over the 4 heads: lanes {L, L^8, L^16, L^24}
#pragma unroll
    for (int c = 0; c < 4; c++) {
        y[c] += __shfl_xor_sync(0xffffffffu, y[c], 8);
        y[c] += __shfl_xor_sync(0xffffffffu, y[c], 16);
    }
    float hv[4];
#pragma unroll
    for (int c = 0; c < 4; c++) hv[c] = fmaxf(0.25f * y[c], 0.f);
    // lane L holds hv for dims (L&7)*4..+3 (replicated across head groups)

    int d0 = (lane & 7) * 4;
    float p16[16] = {};
#pragma unroll
    for (int c = 0; c < 4; c++) {
        float h = hv[c];
        const float4* wrow = (const float4*)&W2[(d0 + c) * 16];
#pragma unroll
        for (int q = 0; q < 4; q++) {
            float4 w = __ldg(&wrow[q]);
            p16[q * 4 + 0] = fmaf(h, w.x, p16[q * 4 + 0]);
            p16[q * 4 + 1] = fmaf(h, w.y, p16[q * 4 + 1]);
            p16[q * 4 + 2] = fmaf(h, w.z, p16[q * 4 + 2]);
            p16[q * 4 + 3] = fmaf(h, w.w, p16[q * 4 + 3]);
        }
    }
    // reduce across the 8 lanes of each group
#pragma unroll
    for (int o = 1; o <= 4; o <<= 1)
#pragma unroll
        for (int j = 0; j < 16; j++)
            p16[j] += __shfl_xor_sync(0xffffffffu, p16[j], o);
    // every lane now holds full feat2[n][0..15]
    if (lane < 4) {
        float4 o4 = make_float4(p16[lane * 4], p16[lane * 4 + 1],
                                p16[lane * 4 + 2], p16[lane * 4 + 3]);
        *(float4*)&g_feat2[n * 16 + lane * 4] = o4;
    }
    if (lane == 0) {
        float el2 = 0.f, er2 = 0.f;
#pragma unroll
        for (int j = 0; j < 16; j++) {
            el2 = fmaf(p16[j], al2[j], el2);
            er2 = fmaf(p16[j], ar2[j], er2);
        }
        g_el2[n] = el2;
        g_er2[n] = er2;
    }
}

// ---------------- agg2: layer-2 softmax+aggregate (4 lanes per dst node) ---
__global__ void agg2_kernel(const float* __restrict__ b2, float* __restrict__ out) {
    int t = blockIdx.x * blockDim.x + threadIdx.x;
    int n = t >> 2;
    if (n >= Nn) return;
    int c = (t & 3) * 4;
    int start = g_offs[n];
    int end = start + g_counts[n];
    float er = g_er2[n];
    float denom = 0.f;
    float4 acc = make_float4(0.f, 0.f, 0.f, 0.f);
#pragma unroll 8
    for (int p = start; p < end; p++) {
        int s = __ldg(&g_csr_src[p]);
        float ex = __expf(leaky02(__ldg(&g_el2[s]) + er));
        denom += ex;
        float4 f = *(const float4*)&g_feat2[s * 16 + c];
        acc.x = fmaf(ex, f.x, acc.x);
        acc.y = fmaf(ex, f.y, acc.y);
        acc.z = fmaf(ex, f.z, acc.z);
        acc.w = fmaf(ex, f.w, acc.w);
    }
    float inv = (denom > 0.f) ? __frcp_rn(denom) : 0.f;
    float4 bv = *(const float4*)&b2[c];
    float4 o4 = make_float4(fmaf(acc.x, inv, bv.x), fmaf(acc.y, inv, bv.y),
                            fmaf(acc.z, inv, bv.z), fmaf(acc.w, inv, bv.w));
    *(float4*)&out[n * 16 + c] = o4;
}

// ---------------- launch ----------------------------------------------------
extern "C" void kernel_launch(void* const* d_in, const int* in_sizes, int n_in,
                              void* d_out, int out_size) {
    const float* x   = (const float*)d_in[0];
    const int*   src = (const int*)d_in[1];
    const int*   dst = (const int*)d_in[2];
    const float* W1  = (const float*)d_in[3];
    const float* al1 = (const float*)d_in[4];
    const float* ar1 = (const float*)d_in[5];
    const float* b1  = (const float*)d_in[6];
    const float* W2  = (const float*)d_in[7];
    const float* al2 = (const float*)d_in[8];
    const float* ar2 = (const float*)d_in[9];
    const float* b2  = (const float*)d_in[10];
    float* out = (float*)d_out;

    init_kernel<<<NB, 256>>>();
    hist_kernel<<<(Ee + 255) / 256, 256>>>(dst);
    scan_block_kernel<<<NB, 256>>>();
    gemm1_kernel<<<GB1, 256>>>(x, W1, al1, ar1);   // 4th launch → profiled slot
    scan_sums_kernel<<<1, 512>>>();
    scan_add_kernel<<<NB, 256>>>();
    fill_kernel<<<(Ee + 255) / 256, 256>>>(src, dst);
    agg1_kernel<<<(Nn * 32 + 255) / 256, 256>>>(b1, W2, al2, ar2);
    agg2_kernel<<<(Nn * 4 + 255) / 256, 256>>>(b2, out);
}

// round 13
// speedup vs baseline: 1.1913x; 1.1551x over previous
#include <cuda_runtime.h>
#include <cuda_fp16.h>

#define Nn 100000
#define Ee 1600000
#define NB 391            // ceil(Nn/256) scan blocks
#define MTILE 128
#define GB1 ((Nn + MTILE - 1) / MTILE)   // 782
#define XS_STRIDE 136     // halves; 272B rows -> 16B aligned, ldmatrix conflict-free
#define WK_STRIDE 136
#define SMEM_BYTES ((MTILE * XS_STRIDE + 128 * WK_STRIDE) * 2)

// ---------------- scratch (device globals; allocation-free) ----------------
__device__ float g_feat1[Nn * 128];   // layer1 projected features [N,4,32]
__device__ float g_el1[Nn * 4];
__device__ float g_er1[Nn * 4];
__device__ float g_feat2[Nn * 16];    // layer2 projected features
__device__ float g_el2[Nn];
__device__ float g_er2[Nn];
__device__ __half g_wh[128 * 128];    // W1 in fp16, k-major [k][col]
// CSR by dst
__device__ int g_counts[Nn];
__device__ int g_offs[Nn];
__device__ int g_cursor[Nn];
__device__ int g_bsums[NB];
__device__ int g_csr_src[Ee];

__device__ __forceinline__ float leaky02(float x) {
    return x > 0.f ? x : 0.2f * x;
}

// ---------------- init: zero CSR counts ------------------------------------
__global__ void init_kernel() {
    int i = blockIdx.x * blockDim.x + threadIdx.x;
    if (i < Nn) g_counts[i] = 0;
}

// ---------------- W1 -> fp16 ------------------------------------------------
__global__ void wconv_kernel(const float* __restrict__ W1) {
    int i = blockIdx.x * blockDim.x + threadIdx.x;  // 16384 elems
    if (i < 128 * 128) g_wh[i] = __float2half(W1[i]);
}

// ---------------- GEMM1 via HMMA (m16n8k16) + el/er epilogue ---------------
// feat1 = x @ W1 (100000x128 @ 128x128), fp16 inputs, fp32 accum.
__global__ void __launch_bounds__(256) gemm1_kernel(
        const float* __restrict__ x,
        const float* __restrict__ al1, const float* __restrict__ ar1) {
    extern __shared__ __half smem[];
    __half* xs = smem;                       // [MTILE][XS_STRIDE]
    __half* wk = smem + MTILE * XS_STRIDE;   // [128][WK_STRIDE]
    int tid = threadIdx.x;
    int nblk = blockIdx.x * MTILE;

    // load x tile (128 nodes x 128 k) as fp16
    const float4* x4 = (const float4*)x;
#pragma unroll
    for (int r = 0; r < 16; r++) {
        int fi = tid + r * 256;          // float4 index 0..4095
        int row = fi >> 5;               // node 0..127
        int c4 = fi & 31;                // group of 4 k
        int n = nblk + row;
        float4 v = (n < Nn) ? x4[n * 32 + c4] : make_float4(0.f, 0.f, 0.f, 0.f);
        __half2 h0 = __floats2half2_rn(v.x, v.y);
        __half2 h1 = __floats2half2_rn(v.z, v.w);
        uint2 st;
        st.x = *(unsigned*)&h0;
        st.y = *(unsigned*)&h1;
        *(uint2*)&xs[row * XS_STRIDE + c4 * 4] = st;
    }
    // load W fp16 (k-major) into smem
    const uint4* wh8 = (const uint4*)g_wh;   // 8 halves each, 2048 total
#pragma unroll
    for (int r = 0; r < 8; r++) {
        int i = tid + r * 256;           // 0..2047
        int row = i >> 4;                // k row
        int c8 = i & 15;                 // group of 8 cols
        *(uint4*)&wk[row * WK_STRIDE + c8 * 8] = wh8[i];
    }
    __syncthreads();

    int lane = tid & 31, wid = tid >> 5;
    int row0 = wid * 16;                 // this warp's 16 nodes

    unsigned xs_u = (unsigned)__cvta_generic_to_shared(xs);
    unsigned wk_u = (unsigned)__cvta_generic_to_shared(wk);
    // A ldmatrix addr: row = row0 + (lane&15); k-offset 8 if lane>=16
    unsigned a_base = xs_u + ((row0 + (lane & 15)) * XS_STRIDE + ((lane >> 4) << 3)) * 2;
    // B ldmatrix addr (x4.trans, 2 n-tiles): k row = (lane&7) + 8*((lane>>3)&1);
    // col-offset 8 if lane>=16
    unsigned b_base = wk_u + (((lane & 7) + (((lane >> 3) & 1) << 3)) * WK_STRIDE
                              + ((lane >> 4) << 3)) * 2;

    float c[16][4];
#pragma unroll
    for (int t = 0; t < 16; t++)
#pragma unroll
        for (int j = 0; j < 4; j++) c[t][j] = 0.f;

#pragma unroll
    for (int kc = 0; kc < 8; kc++) {
        unsigned a0r, a1r, a2r, a3r;
        asm volatile("ldmatrix.sync.aligned.m8n8.x4.shared.b16 {%0,%1,%2,%3}, [%4];"
                     : "=r"(a0r), "=r"(a1r), "=r"(a2r), "=r"(a3r)
                     : "r"(a_base + kc * 32));
#pragma unroll
        for (int np = 0; np < 8; np++) {   // pairs of n-tiles
            unsigned b0, b1, b2, b3;
            asm volatile("ldmatrix.sync.aligned.m8n8.x4.trans.shared.b16 {%0,%1,%2,%3}, [%4];"
                         : "=r"(b0), "=r"(b1), "=r"(b2), "=r"(b3)
                         : "r"(b_base + kc * 16 * WK_STRIDE * 2 + np * 32));
            int t0 = np * 2, t1 = np * 2 + 1;
            asm volatile("mma.sync.aligned.m16n8k16.row.col.f32.f16.f16.f32 "
                         "{%0,%1,%2,%3}, {%4,%5,%6,%7}, {%8,%9}, {%0,%1,%2,%3};"
                         : "+f"(c[t0][0]), "+f"(c[t0][1]), "+f"(c[t0][2]), "+f"(c[t0][3])
                         : "r"(a0r), "r"(a1r), "r"(a2r), "r"(a3r), "r"(b0), "r"(b1));
            asm volatile("mma.sync.aligned.m16n8k16.row.col.f32.f16.f16.f32 "
                         "{%0,%1,%2,%3}, {%4,%5,%6,%7}, {%8,%9}, {%0,%1,%2,%3};"
                         : "+f"(c[t1][0]), "+f"(c[t1][1]), "+f"(c[t1][2]), "+f"(c[t1][3])
                         : "r"(a0r), "r"(a1r), "r"(a2r), "r"(a3r), "r"(b2), "r"(b3));
        }
    }

    // epilogue: store feat1 (fp32) + el/er per head
    int q = lane & 3;          // col sub-index
    int r = lane >> 2;         // row 0..7 within tile
    int n1 = nblk + row0 + r;
    int n2 = n1 + 8;
    float elp[8] = {0.f, 0.f, 0.f, 0.f, 0.f, 0.f, 0.f, 0.f};
    float erp[8] = {0.f, 0.f, 0.f, 0.f, 0.f, 0.f, 0.f, 0.f};
#pragma unroll
    for (int nt = 0; nt < 16; nt++) {
        int col = nt * 8 + q * 2;
        int head = nt >> 2;    // col/32, uniform per tile
        float a0 = __ldg(&al1[col]), a1 = __ldg(&al1[col + 1]);
        float r0 = __ldg(&ar1[col]), r1 = __ldg(&ar1[col + 1]);
        elp[head]     += c[nt][0] * a0 + c[nt][1] * a1;
        erp[head]     += c[nt][0] * r0 + c[nt][1] * r1;
        elp[4 + head] += c[nt][2] * a0 + c[nt][3] * a1;
        erp[4 + head] += c[nt][2] * r0 + c[nt][3] * r1;
        if (n1 < Nn) {
            float2 o = make_float2(c[nt][0], c[nt][1]);
            *(float2*)&g_feat1[n1 * 128 + col] = o;
        }
        if (n2 < Nn) {
            float2 o = make_float2(c[nt][2], c[nt][3]);
            *(float2*)&g_feat1[n2 * 128 + col] = o;
        }
    }
    // reduce over the 4 lanes sharing a row
#pragma unroll
    for (int h = 0; h < 8; h++) {
        elp[h] += __shfl_xor_sync(0xffffffffu, elp[h], 1);
        elp[h] += __shfl_xor_sync(0xffffffffu, elp[h], 2);
        erp[h] += __shfl_xor_sync(0xffffffffu, erp[h], 1);
        erp[h] += __shfl_xor_sync(0xffffffffu, erp[h], 2);
    }
    // lane with sub-index q writes head q
    if (n1 < Nn) { g_el1[n1 * 4 + q] = elp[q];     g_er1[n1 * 4 + q] = erp[q]; }
    if (n2 < Nn) { g_el1[n2 * 4 + q] = elp[4 + q]; g_er1[n2 * 4 + q] = erp[4 + q]; }
}

// ---------------- CSR build -------------------------------------------------
__global__ void hist_kernel(const int* __restrict__ dst) {
    int e = blockIdx.x * blockDim.x + threadIdx.x;
    if (e < Ee) atomicAdd(&g_counts[dst[e]], 1);
}

__global__ void scan_block_kernel() {
    __shared__ int sh[256];
    int t = threadIdx.x;
    int i = blockIdx.x * 256 + t;
    int v = (i < Nn) ? g_counts[i] : 0;
    sh[t] = v;
    __syncthreads();
    for (int off = 1; off < 256; off <<= 1) {
        int add = (t >= off) ? sh[t - off] : 0;
        __syncthreads();
        sh[t] += add;
        __syncthreads();
    }
    if (i < Nn) g_offs[i] = sh[t] - v;        // exclusive within block
    if (t == 255) g_bsums[blockIdx.x] = sh[t];
}

__global__ void scan_sums_kernel() {
    __shared__ int sh[512];
    int t = threadIdx.x;
    int v = (t < NB) ? g_bsums[t] : 0;
    sh[t] = v;
    __syncthreads();
    for (int off = 1; off < 512; off <<= 1) {
        int add = (t >= off) ? sh[t - off] : 0;
        __syncthreads();
        sh[t] += add;
        __syncthreads();
    }
    if (t < NB) g_bsums[t] = sh[t] - v;       // exclusive
}

__global__ void scan_add_kernel() {
    int i = blockIdx.x * 256 + threadIdx.x;
    if (i < Nn) {
        int o = g_offs[i] + g_bsums[i >> 8];
        g_offs[i] = o;
        g_cursor[i] = o;
    }
}

__global__ void fill_kernel(const int* __restrict__ src, const int* __restrict__ dst) {
    int e = blockIdx.x * blockDim.x + threadIdx.x;
    if (e < Ee) {
        int s = src[e];
        int p = atomicAdd(&g_cursor[dst[e]], 1);
        g_csr_src[p] = s;
    }
}

// ---------------- agg1: fused softmax+aggregate+mid (warp per dst node) ----
__global__ void agg1_kernel(const float* __restrict__ b1, const float* __restrict__ W2,
                            const float* __restrict__ al2, const float* __restrict__ ar2) {
    int n = (blockIdx.x * blockDim.x + threadIdx.x) >> 5;
    int lane = threadIdx.x & 31;
    if (n >= Nn) return;
    int head = lane >> 3;
    int start = g_offs[n];
    int end = start + g_counts[n];
    float er = g_er1[n * 4 + head];
    float denom = 0.f;
    float4 acc = make_float4(0.f, 0.f, 0.f, 0.f);

#pragma unroll 8
    for (int p = start; p < end; p++) {
        int s = __ldg(&g_csr_src[p]);               // warp-broadcast load
        float el = __ldg(&g_el1[s * 4 + head]);
        float ex = __expf(leaky02(el + er));
        denom += ex;
        float4 f = *(const float4*)&g_feat1[s * 128 + lane * 4];  // coalesced 512B
        acc.x = fmaf(ex, f.x, acc.x);
        acc.y = fmaf(ex, f.y, acc.y);
        acc.z = fmaf(ex, f.z, acc.z);
        acc.w = fmaf(ex, f.w, acc.w);
    }
    float inv = (denom > 0.f) ? __frcp_rn(denom) : 0.f;
    float4 bv = *(const float4*)&b1[lane * 4];
    float y[4] = {fmaf(acc.x, inv, bv.x), fmaf(acc.y, inv, bv.y),
                  fmaf(acc.z, inv, bv.z), fmaf(acc.w, inv, bv.w)};
#pragma unroll
    for (int c = 0; c < 4; c++) {
        y[c] += __shfl_xor_sync(0xffffffffu, y[c], 8);
        y[c] += __shfl_xor_sync(0xffffffffu, y[c], 16);
    }
    float hv[4];
#pragma unroll
    for (int c = 0; c < 4; c++) hv[c] = fmaxf(0.25f * y[c], 0.f);

    int d0 = (lane & 7) * 4;
    float p16[16] = {};
#pragma unroll
    for (int c = 0; c < 4; c++) {
        float h = hv[c];
        const float4* wrow = (const float4*)&W2[(d0 + c) * 16];
#pragma unroll
        for (int qq = 0; qq < 4; qq++) {
            float4 w = __ldg(&wrow[qq]);
            p16[qq * 4 + 0] = fmaf(h, w.x, p16[qq * 4 + 0]);
            p16[qq * 4 + 1] = fmaf(h, w.y, p16[qq * 4 + 1]);
            p16[qq * 4 + 2] = fmaf(h, w.z, p16[qq * 4 + 2]);
            p16[qq * 4 + 3] = fmaf(h, w.w, p16[qq * 4 + 3]);
        }
    }
#pragma unroll
    for (int o = 1; o <= 4; o <<= 1)
#pragma unroll
        for (int j = 0; j < 16; j++)
            p16[j] += __shfl_xor_sync(0xffffffffu, p16[j], o);
    if (lane < 4) {
        float4 o4 = make_float4(p16[lane * 4], p16[lane * 4 + 1],
                                p16[lane * 4 + 2], p16[lane * 4 + 3]);
        *(float4*)&g_feat2[n * 16 + lane * 4] = o4;
    }
    if (lane == 0) {
        float el2 = 0.f, er2 = 0.f;
#pragma unroll
        for (int j = 0; j < 16; j++) {
            el2 = fmaf(p16[j], al2[j], el2);
            er2 = fmaf(p16[j], ar2[j], er2);
        }
        g_el2[n] = el2;
        g_er2[n] = er2;
    }
}

// ---------------- agg2: layer-2 softmax+aggregate (4 lanes per dst node) ---
__global__ void agg2_kernel(const float* __restrict__ b2, float* __restrict__ out) {
    int t = blockIdx.x * blockDim.x + threadIdx.x;
    int n = t >> 2;
    if (n >= Nn) return;
    int c = (t & 3) * 4;
    int start = g_offs[n];
    int end = start + g_counts[n];
    float er = g_er2[n];
    float denom = 0.f;
    float4 acc = make_float4(0.f, 0.f, 0.f, 0.f);
#pragma unroll 8
    for (int p = start; p < end; p++) {
        int s = __ldg(&g_csr_src[p]);
        float ex = __expf(leaky02(__ldg(&g_el2[s]) + er));
        denom += ex;
        float4 f = *(const float4*)&g_feat2[s * 16 + c];
        acc.x = fmaf(ex, f.x, acc.x);
        acc.y = fmaf(ex, f.y, acc.y);
        acc.z = fmaf(ex, f.z, acc.z);
        acc.w = fmaf(ex, f.w, acc.w);
    }
    float inv = (denom > 0.f) ? __frcp_rn(denom) : 0.f;
    float4 bv = *(const float4*)&b2[c];
    float4 o4 = make_float4(fmaf(acc.x, inv, bv.x), fmaf(acc.y, inv, bv.y),
                            fmaf(acc.z, inv, bv.z), fmaf(acc.w, inv, bv.w));
    *(float4*)&out[n * 16 + c] = o4;
}

// ---------------- launch ----------------------------------------------------
extern "C" void kernel_launch(void* const* d_in, const int* in_sizes, int n_in,
                              void* d_out, int out_size) {
    const float* x   = (const float*)d_in[0];
    const int*   src = (const int*)d_in[1];
    const int*   dst = (const int*)d_in[2];
    const float* W1  = (const float*)d_in[3];
    const float* al1 = (const float*)d_in[4];
    const float* ar1 = (const float*)d_in[5];
    const float* b1  = (const float*)d_in[6];
    const float* W2  = (const float*)d_in[7];
    const float* al2 = (const float*)d_in[8];
    const float* ar2 = (const float*)d_in[9];
    const float* b2  = (const float*)d_in[10];
    float* out = (float*)d_out;

    cudaFuncSetAttribute(gemm1_kernel,
                         cudaFuncAttributeMaxDynamicSharedMemorySize, SMEM_BYTES);

    init_kernel<<<NB, 256>>>();
    wconv_kernel<<<64, 256>>>(W1);
    hist_kernel<<<(Ee + 255) / 256, 256>>>(dst);
    gemm1_kernel<<<GB1, 256, SMEM_BYTES>>>(x, al1, ar1);   // 4th launch → profiled
    scan_block_kernel<<<NB, 256>>>();
    scan_sums_kernel<<<1, 512>>>();
    scan_add_kernel<<<NB, 256>>>();
    fill_kernel<<<(Ee + 255) / 256, 256>>>(src, dst);
    agg1_kernel<<<(Nn * 32 + 255) / 256, 256>>>(b1, W2, al2, ar2);
    agg2_kernel<<<(Nn * 4 + 255) / 256, 256>>>(b2, out);
}

// round 14
// speedup vs baseline: 1.9491x; 1.6361x over previous
#include <cuda_runtime.h>
#include <cuda_fp16.h>

#define Nn 100000
#define Ee 1600000
#define NB 391            // ceil(Nn/256) scan blocks
#define MTILE 128
#define GB1 ((Nn + MTILE - 1) / MTILE)   // 782
#define XS_STRIDE 136     // halves; 272B rows -> 16B aligned, ldmatrix conflict-free
#define WK_STRIDE 136
#define SMEM_BYTES ((MTILE * XS_STRIDE + 128 * WK_STRIDE) * 2)

// ---------------- scratch (device globals; allocation-free) ----------------
__device__ float g_feat1[Nn * 128];   // layer1 projected features [N,4,32]
__device__ float g_el1[Nn * 4];
__device__ float g_er1[Nn * 4];
__device__ float g_h[Nn * 32];        // post head-mean + relu hidden vector
__device__ float g_feat2[Nn * 16];    // layer2 projected features
__device__ float g_el2[Nn];
__device__ float g_er2[Nn];
__device__ __half g_wh[128 * 128];    // W1 in fp16, k-major [k][col]
// CSR by dst  (g_counts statically zero-initialized; re-zeroed by agg2)
__device__ int g_counts[Nn];
__device__ int g_offs[Nn];
__device__ int g_cursor[Nn];
__device__ int g_bsums[NB];
__device__ int g_csr_src[Ee];

__device__ __forceinline__ float leaky02(float x) {
    return x > 0.f ? x : 0.2f * x;
}

// ---------------- W1 -> fp16 ------------------------------------------------
__global__ void wconv_kernel(const float* __restrict__ W1) {
    int i = blockIdx.x * blockDim.x + threadIdx.x;  // 16384 elems
    if (i < 128 * 128) g_wh[i] = __float2half(W1[i]);
}

// ---------------- GEMM1 via HMMA (m16n8k16) + el/er epilogue ---------------
__global__ void __launch_bounds__(256) gemm1_kernel(
        const float* __restrict__ x,
        const float* __restrict__ al1, const float* __restrict__ ar1) {
    extern __shared__ __half smem[];
    __half* xs = smem;                       // [MTILE][XS_STRIDE]
    __half* wk = smem + MTILE * XS_STRIDE;   // [128][WK_STRIDE]
    int tid = threadIdx.x;
    int nblk = blockIdx.x * MTILE;

    const float4* x4 = (const float4*)x;
#pragma unroll
    for (int r = 0; r < 16; r++) {
        int fi = tid + r * 256;          // float4 index 0..4095
        int row = fi >> 5;               // node 0..127
        int c4 = fi & 31;                // group of 4 k
        int n = nblk + row;
        float4 v = (n < Nn) ? x4[n * 32 + c4] : make_float4(0.f, 0.f, 0.f, 0.f);
        __half2 h0 = __floats2half2_rn(v.x, v.y);
        __half2 h1 = __floats2half2_rn(v.z, v.w);
        uint2 st;
        st.x = *(unsigned*)&h0;
        st.y = *(unsigned*)&h1;
        *(uint2*)&xs[row * XS_STRIDE + c4 * 4] = st;
    }
    const uint4* wh8 = (const uint4*)g_wh;   // 8 halves each, 2048 total
#pragma unroll
    for (int r = 0; r < 8; r++) {
        int i = tid + r * 256;           // 0..2047
        int row = i >> 4;                // k row
        int c8 = i & 15;                 // group of 8 cols
        *(uint4*)&wk[row * WK_STRIDE + c8 * 8] = wh8[i];
    }
    __syncthreads();

    int lane = tid & 31, wid = tid >> 5;
    int row0 = wid * 16;

    unsigned xs_u = (unsigned)__cvta_generic_to_shared(xs);
    unsigned wk_u = (unsigned)__cvta_generic_to_shared(wk);
    unsigned a_base = xs_u + ((row0 + (lane & 15)) * XS_STRIDE + ((lane >> 4) << 3)) * 2;
    unsigned b_base = wk_u + (((lane & 7) + (((lane >> 3) & 1) << 3)) * WK_STRIDE
                              + ((lane >> 4) << 3)) * 2;

    float c[16][4];
#pragma unroll
    for (int t = 0; t < 16; t++)
#pragma unroll
        for (int j = 0; j < 4; j++) c[t][j] = 0.f;

#pragma unroll
    for (int kc = 0; kc < 8; kc++) {
        unsigned a0r, a1r, a2r, a3r;
        asm volatile("ldmatrix.sync.aligned.m8n8.x4.shared.b16 {%0,%1,%2,%3}, [%4];"
                     : "=r"(a0r), "=r"(a1r), "=r"(a2r), "=r"(a3r)
                     : "r"(a_base + kc * 32));
#pragma unroll
        for (int np = 0; np < 8; np++) {
            unsigned b0, b1, b2, b3;
            asm volatile("ldmatrix.sync.aligned.m8n8.x4.trans.shared.b16 {%0,%1,%2,%3}, [%4];"
                         : "=r"(b0), "=r"(b1), "=r"(b2), "=r"(b3)
                         : "r"(b_base + kc * 16 * WK_STRIDE * 2 + np * 32));
            int t0 = np * 2, t1 = np * 2 + 1;
            asm volatile("mma.sync.aligned.m16n8k16.row.col.f32.f16.f16.f32 "
                         "{%0,%1,%2,%3}, {%4,%5,%6,%7}, {%8,%9}, {%0,%1,%2,%3};"
                         : "+f"(c[t0][0]), "+f"(c[t0][1]), "+f"(c[t0][2]), "+f"(c[t0][3])
                         : "r"(a0r), "r"(a1r), "r"(a2r), "r"(a3r), "r"(b0), "r"(b1));
            asm volatile("mma.sync.aligned.m16n8k16.row.col.f32.f16.f16.f32 "
                         "{%0,%1,%2,%3}, {%4,%5,%6,%7}, {%8,%9}, {%0,%1,%2,%3};"
                         : "+f"(c[t1][0]), "+f"(c[t1][1]), "+f"(c[t1][2]), "+f"(c[t1][3])
                         : "r"(a0r), "r"(a1r), "r"(a2r), "r"(a3r), "r"(b2), "r"(b3));
        }
    }

    int q = lane & 3;
    int r = lane >> 2;
    int n1 = nblk + row0 + r;
    int n2 = n1 + 8;
    float elp[8] = {0.f, 0.f, 0.f, 0.f, 0.f, 0.f, 0.f, 0.f};
    float erp[8] = {0.f, 0.f, 0.f, 0.f, 0.f, 0.f, 0.f, 0.f};
#pragma unroll
    for (int nt = 0; nt < 16; nt++) {
        int col = nt * 8 + q * 2;
        int head = nt >> 2;
        float a0 = __ldg(&al1[col]), a1 = __ldg(&al1[col + 1]);
        float r0 = __ldg(&ar1[col]), r1 = __ldg(&ar1[col + 1]);
        elp[head]     += c[nt][0] * a0 + c[nt][1] * a1;
        erp[head]     += c[nt][0] * r0 + c[nt][1] * r1;
        elp[4 + head] += c[nt][2] * a0 + c[nt][3] * a1;
        erp[4 + head] += c[nt][2] * r0 + c[nt][3] * r1;
        if (n1 < Nn) {
            float2 o = make_float2(c[nt][0], c[nt][1]);
            *(float2*)&g_feat1[n1 * 128 + col] = o;
        }
        if (n2 < Nn) {
            float2 o = make_float2(c[nt][2], c[nt][3]);
            *(float2*)&g_feat1[n2 * 128 + col] = o;
        }
    }
#pragma unroll
    for (int h = 0; h < 8; h++) {
        elp[h] += __shfl_xor_sync(0xffffffffu, elp[h], 1);
        elp[h] += __shfl_xor_sync(0xffffffffu, elp[h], 2);
        erp[h] += __shfl_xor_sync(0xffffffffu, erp[h], 1);
        erp[h] += __shfl_xor_sync(0xffffffffu, erp[h], 2);
    }
    if (n1 < Nn) { g_el1[n1 * 4 + q] = elp[q];     g_er1[n1 * 4 + q] = erp[q]; }
    if (n2 < Nn) { g_el1[n2 * 4 + q] = elp[4 + q]; g_er1[n2 * 4 + q] = erp[4 + q]; }
}

// ---------------- CSR build -------------------------------------------------
__global__ void hist_kernel(const int* __restrict__ dst) {
    int e = blockIdx.x * blockDim.x + threadIdx.x;
    if (e < Ee) atomicAdd(&g_counts[dst[e]], 1);
}

__global__ void scan_block_kernel() {
    __shared__ int sh[256];
    int t = threadIdx.x;
    int i = blockIdx.x * 256 + t;
    int v = (i < Nn) ? g_counts[i] : 0;
    sh[t] = v;
    __syncthreads();
    for (int off = 1; off < 256; off <<= 1) {
        int add = (t >= off) ? sh[t - off] : 0;
        __syncthreads();
        sh[t] += add;
        __syncthreads();
    }
    if (i < Nn) g_offs[i] = sh[t] - v;        // exclusive within block
    if (t == 255) g_bsums[blockIdx.x] = sh[t];
}

__global__ void scan_sums_kernel() {
    __shared__ int sh[512];
    int t = threadIdx.x;
    int v = (t < NB) ? g_bsums[t] : 0;
    sh[t] = v;
    __syncthreads();
    for (int off = 1; off < 512; off <<= 1) {
        int add = (t >= off) ? sh[t - off] : 0;
        __syncthreads();
        sh[t] += add;
        __syncthreads();
    }
    if (t < NB) g_bsums[t] = sh[t] - v;       // exclusive
}

__global__ void scan_add_kernel() {
    int i = blockIdx.x * 256 + threadIdx.x;
    if (i < Nn) {
        int o = g_offs[i] + g_bsums[i >> 8];
        g_offs[i] = o;
        g_cursor[i] = o;
    }
}

__global__ void fill_kernel(const int* __restrict__ src, const int* __restrict__ dst) {
    int e = blockIdx.x * blockDim.x + threadIdx.x;
    if (e < Ee) {
        int s = src[e];
        int p = atomicAdd(&g_cursor[dst[e]], 1);
        g_csr_src[p] = s;
    }
}

// ---------------- agg1: lean gather+softmax+head-mean (warp per dst node) --
// Writes g_h[n][32] = relu(mean_heads(softmax-agg + b1)). Heavy epilogue moved
// to mid_kernel to keep registers low and occupancy high.
__global__ void __launch_bounds__(256) agg1_kernel(const float* __restrict__ b1) {
    int n = (blockIdx.x * blockDim.x + threadIdx.x) >> 5;
    int lane = threadIdx.x & 31;
    if (n >= Nn) return;
    int head = lane >> 3;
    int start = g_offs[n];
    int end = start + g_counts[n];
    float er = g_er1[n * 4 + head];
    float denom = 0.f;
    float4 acc = make_float4(0.f, 0.f, 0.f, 0.f);

#pragma unroll 4
    for (int p = start; p < end; p++) {
        int s = __ldg(&g_csr_src[p]);               // warp-broadcast, L1-resident
        float el = __ldg(&g_el1[s * 4 + head]);
        float ex = __expf(leaky02(el + er));
        denom += ex;
        float4 f = __ldcg((const float4*)&g_feat1[s * 128 + lane * 4]);  // L2-only
        acc.x = fmaf(ex, f.x, acc.x);
        acc.y = fmaf(ex, f.y, acc.y);
        acc.z = fmaf(ex, f.z, acc.z);
        acc.w = fmaf(ex, f.w, acc.w);
    }
    float inv = (denom > 0.f) ? __frcp_rn(denom) : 0.f;
    float4 bv = *(const float4*)&b1[lane * 4];
    float y0 = fmaf(acc.x, inv, bv.x);
    float y1 = fmaf(acc.y, inv, bv.y);
    float y2 = fmaf(acc.z, inv, bv.z);
    float y3 = fmaf(acc.w, inv, bv.w);
    // mean over 4 heads: lanes {L, L^8, L^16, L^24}
    y0 += __shfl_xor_sync(0xffffffffu, y0, 8);
    y1 += __shfl_xor_sync(0xffffffffu, y1, 8);
    y2 += __shfl_xor_sync(0xffffffffu, y2, 8);
    y3 += __shfl_xor_sync(0xffffffffu, y3, 8);
    y0 += __shfl_xor_sync(0xffffffffu, y0, 16);
    y1 += __shfl_xor_sync(0xffffffffu, y1, 16);
    y2 += __shfl_xor_sync(0xffffffffu, y2, 16);
    y3 += __shfl_xor_sync(0xffffffffu, y3, 16);
    if (lane < 8) {
        float4 o = make_float4(fmaxf(0.25f * y0, 0.f), fmaxf(0.25f * y1, 0.f),
                               fmaxf(0.25f * y2, 0.f), fmaxf(0.25f * y3, 0.f));
        *(float4*)&g_h[n * 32 + lane * 4] = o;
    }
}

// ---------------- mid: GEMM2 (32->16) + el2/er2 (warp per node) ------------
__global__ void mid_kernel(const float* __restrict__ W2,
                           const float* __restrict__ al2, const float* __restrict__ ar2) {
    int n = (blockIdx.x * blockDim.x + threadIdx.x) >> 5;
    int lane = threadIdx.x & 31;   // = hidden dim d
    if (n >= Nn) return;
    float hv = g_h[n * 32 + lane];    // coalesced 128B
    float p16[16];
    const float4* wrow = (const float4*)&W2[lane * 16];
#pragma unroll
    for (int q = 0; q < 4; q++) {
        float4 w = __ldg(&wrow[q]);
        p16[q * 4 + 0] = hv * w.x;
        p16[q * 4 + 1] = hv * w.y;
        p16[q * 4 + 2] = hv * w.z;
        p16[q * 4 + 3] = hv * w.w;
    }
#pragma unroll
    for (int o = 1; o <= 16; o <<= 1)
#pragma unroll
        for (int j = 0; j < 16; j++)
            p16[j] += __shfl_xor_sync(0xffffffffu, p16[j], o);
    // every lane holds full feat2[n][0..15]
    if (lane < 4) {
        float4 o4 = make_float4(p16[lane * 4], p16[lane * 4 + 1],
                                p16[lane * 4 + 2], p16[lane * 4 + 3]);
        *(float4*)&g_feat2[n * 16 + lane * 4] = o4;
    }
    if (lane == 0) {
        float el2 = 0.f, er2 = 0.f;
#pragma unroll
        for (int j = 0; j < 16; j++) {
            el2 = fmaf(p16[j], __ldg(&al2[j]), el2);
            er2 = fmaf(p16[j], __ldg(&ar2[j]), er2);
        }
        g_el2[n] = el2;
        g_er2[n] = er2;
    }
}

// ---------------- agg2: layer-2 softmax+aggregate (4 lanes per dst node) ---
__global__ void agg2_kernel(const float* __restrict__ b2, float* __restrict__ out) {
    int t = blockIdx.x * blockDim.x + threadIdx.x;
    int n = t >> 2;
    if (n >= Nn) return;
    int c = (t & 3) * 4;
    int start = g_offs[n];
    int end = start + g_counts[n];
    float er = g_er2[n];
    float denom = 0.f;
    float4 acc = make_float4(0.f, 0.f, 0.f, 0.f);
#pragma unroll 4
    for (int p = start; p < end; p++) {
        int s = __ldg(&g_csr_src[p]);
        float ex = __expf(leaky02(__ldg(&g_el2[s]) + er));
        denom += ex;
        float4 f = __ldcg((const float4*)&g_feat2[s * 16 + c]);
        acc.x = fmaf(ex, f.x, acc.x);
        acc.y = fmaf(ex, f.y, acc.y);
        acc.z = fmaf(ex, f.z, acc.z);
        acc.w = fmaf(ex, f.w, acc.w);
    }
    float inv = (denom > 0.f) ? __frcp_rn(denom) : 0.f;
    float4 bv = *(const float4*)&b2[c];
    float4 o4 = make_float4(fmaf(acc.x, inv, bv.x), fmaf(acc.y, inv, bv.y),
                            fmaf(acc.z, inv, bv.z), fmaf(acc.w, inv, bv.w));
    *(float4*)&out[n * 16 + c] = o4;
    // reset counts for the next graph replay (statically zero on first run)
    if ((t & 3) == 0) g_counts[n] = 0;
}

// ---------------- launch ----------------------------------------------------
extern "C" void kernel_launch(void* const* d_in, const int* in_sizes, int n_in,
                              void* d_out, int out_size) {
    const float* x   = (const float*)d_in[0];
    const int*   src = (const int*)d_in[1];
    const int*   dst = (const int*)d_in[2];
    const float* W1  = (const float*)d_in[3];
    const float* al1 = (const float*)d_in[4];
    const float* ar1 = (const float*)d_in[5];
    const float* b1  = (const float*)d_in[6];
    const float* W2  = (const float*)d_in[7];
    const float* al2 = (const float*)d_in[8];
    const float* ar2 = (const float*)d_in[9];
    const float* b2  = (const float*)d_in[10];
    float* out = (float*)d_out;

    cudaFuncSetAttribute(gemm1_kernel,
                         cudaFuncAttributeMaxDynamicSharedMemorySize, SMEM_BYTES);

    wconv_kernel<<<64, 256>>>(W1);
    hist_kernel<<<(Ee + 255) / 256, 256>>>(dst);
    scan_block_kernel<<<NB, 256>>>();
    gemm1_kernel<<<GB1, 256, SMEM_BYTES>>>(x, al1, ar1);   // 4th launch → profiled
    scan_sums_kernel<<<1, 512>>>();
    scan_add_kernel<<<NB, 256>>>();
    fill_kernel<<<(Ee + 255) / 256, 256>>>(src, dst);
    agg1_kernel<<<(Nn * 32 + 255) / 256, 256>>>(b1);
    mid_kernel<<<(Nn * 32 + 255) / 256, 256>>>(W2, al2, ar2);
    agg2_kernel<<<(Nn * 4 + 255) / 256, 256>>>(b2, out);
}

// round 15
// speedup vs baseline: 2.0311x; 1.0421x over previous
#include <cuda_runtime.h>
#include <cuda_fp16.h>

#define Nn 100000
#define Ee 1600000
#define NB 391            // ceil(Nn/256) scan blocks
#define MTILE 128
#define GB1 ((Nn + MTILE - 1) / MTILE)   // 782
#define XS_STRIDE 136     // halves; 272B rows -> 16B aligned, ldmatrix conflict-free
#define WK_STRIDE 136
#define SMEM_BYTES ((MTILE * XS_STRIDE + 128 * WK_STRIDE) * 2)

// ---------------- scratch (device globals; allocation-free) ----------------
__device__ unsigned g_feat1h[Nn * 64]; // layer1 features, half2 pairs [N][64]
__device__ float g_el1[Nn * 4];
__device__ float g_er1[Nn * 4];
__device__ float g_h[Nn * 32];        // post head-mean + relu hidden vector
__device__ float g_feat2[Nn * 16];    // layer2 projected features
__device__ float g_el2[Nn];
__device__ float g_er2[Nn];
__device__ __half g_wh[128 * 128];    // W1 in fp16, k-major [k][col]
// CSR by dst  (g_counts statically zero-initialized; re-zeroed by agg2)
__device__ int g_counts[Nn];
__device__ int g_offs[Nn];
__device__ int g_cursor[Nn];
__device__ int g_bsums[NB];
__device__ int g_csr_src[Ee];

__device__ __forceinline__ float leaky02(float x) {
    return x > 0.f ? x : 0.2f * x;
}

// ---------------- W1 -> fp16 ------------------------------------------------
__global__ void wconv_kernel(const float* __restrict__ W1) {
    int i = blockIdx.x * blockDim.x + threadIdx.x;  // 16384 elems
    if (i < 128 * 128) g_wh[i] = __float2half(W1[i]);
}

// ---------------- GEMM1 via HMMA (m16n8k16) + el/er epilogue ---------------
// feat1 stored as half2 (halves gather traffic); el/er from fp32 accumulators.
__global__ void __launch_bounds__(256) gemm1_kernel(
        const float* __restrict__ x,
        const float* __restrict__ al1, const float* __restrict__ ar1) {
    extern __shared__ __half smem[];
    __half* xs = smem;                       // [MTILE][XS_STRIDE]
    __half* wk = smem + MTILE * XS_STRIDE;   // [128][WK_STRIDE]
    int tid = threadIdx.x;
    int nblk = blockIdx.x * MTILE;

    const float4* x4 = (const float4*)x;
#pragma unroll
    for (int r = 0; r < 16; r++) {
        int fi = tid + r * 256;          // float4 index 0..4095
        int row = fi >> 5;               // node 0..127
        int c4 = fi & 31;                // group of 4 k
        int n = nblk + row;
        float4 v = (n < Nn) ? x4[n * 32 + c4] : make_float4(0.f, 0.f, 0.f, 0.f);
        __half2 h0 = __floats2half2_rn(v.x, v.y);
        __half2 h1 = __floats2half2_rn(v.z, v.w);
        uint2 st;
        st.x = *(unsigned*)&h0;
        st.y = *(unsigned*)&h1;
        *(uint2*)&xs[row * XS_STRIDE + c4 * 4] = st;
    }
    const uint4* wh8 = (const uint4*)g_wh;   // 8 halves each, 2048 total
#pragma unroll
    for (int r = 0; r < 8; r++) {
        int i = tid + r * 256;           // 0..2047
        int row = i >> 4;                // k row
        int c8 = i & 15;                 // group of 8 cols
        *(uint4*)&wk[row * WK_STRIDE + c8 * 8] = wh8[i];
    }
    __syncthreads();

    int lane = tid & 31, wid = tid >> 5;
    int row0 = wid * 16;

    unsigned xs_u = (unsigned)__cvta_generic_to_shared(xs);
    unsigned wk_u = (unsigned)__cvta_generic_to_shared(wk);
    unsigned a_base = xs_u + ((row0 + (lane & 15)) * XS_STRIDE + ((lane >> 4) << 3)) * 2;
    unsigned b_base = wk_u + (((lane & 7) + (((lane >> 3) & 1) << 3)) * WK_STRIDE
                              + ((lane >> 4) << 3)) * 2;

    float c[16][4];
#pragma unroll
    for (int t = 0; t < 16; t++)
#pragma unroll
        for (int j = 0; j < 4; j++) c[t][j] = 0.f;

#pragma unroll
    for (int kc = 0; kc < 8; kc++) {
        unsigned a0r, a1r, a2r, a3r;
        asm volatile("ldmatrix.sync.aligned.m8n8.x4.shared.b16 {%0,%1,%2,%3}, [%4];"
                     : "=r"(a0r), "=r"(a1r), "=r"(a2r), "=r"(a3r)
                     : "r"(a_base + kc * 32));
#pragma unroll
        for (int np = 0; np < 8; np++) {
            unsigned b0, b1, b2, b3;
            asm volatile("ldmatrix.sync.aligned.m8n8.x4.trans.shared.b16 {%0,%1,%2,%3}, [%4];"
                         : "=r"(b0), "=r"(b1), "=r"(b2), "=r"(b3)
                         : "r"(b_base + kc * 16 * WK_STRIDE * 2 + np * 32));
            int t0 = np * 2, t1 = np * 2 + 1;
            asm volatile("mma.sync.aligned.m16n8k16.row.col.f32.f16.f16.f32 "
                         "{%0,%1,%2,%3}, {%4,%5,%6,%7}, {%8,%9}, {%0,%1,%2,%3};"
                         : "+f"(c[t0][0]), "+f"(c[t0][1]), "+f"(c[t0][2]), "+f"(c[t0][3])
                         : "r"(a0r), "r"(a1r), "r"(a2r), "r"(a3r), "r"(b0), "r"(b1));
            asm volatile("mma.sync.aligned.m16n8k16.row.col.f32.f16.f16.f32 "
                         "{%0,%1,%2,%3}, {%4,%5,%6,%7}, {%8,%9}, {%0,%1,%2,%3};"
                         : "+f"(c[t1][0]), "+f"(c[t1][1]), "+f"(c[t1][2]), "+f"(c[t1][3])
                         : "r"(a0r), "r"(a1r), "r"(a2r), "r"(a3r), "r"(b2), "r"(b3));
        }
    }

    int q = lane & 3;
    int r = lane >> 2;
    int n1 = nblk + row0 + r;
    int n2 = n1 + 8;
    float elp[8] = {0.f, 0.f, 0.f, 0.f, 0.f, 0.f, 0.f, 0.f};
    float erp[8] = {0.f, 0.f, 0.f, 0.f, 0.f, 0.f, 0.f, 0.f};
#pragma unroll
    for (int nt = 0; nt < 16; nt++) {
        int col = nt * 8 + q * 2;
        int head = nt >> 2;
        float a0 = __ldg(&al1[col]), a1 = __ldg(&al1[col + 1]);
        float r0 = __ldg(&ar1[col]), r1 = __ldg(&ar1[col + 1]);
        elp[head]     += c[nt][0] * a0 + c[nt][1] * a1;
        erp[head]     += c[nt][0] * r0 + c[nt][1] * r1;
        elp[4 + head] += c[nt][2] * a0 + c[nt][3] * a1;
        erp[4 + head] += c[nt][2] * r0 + c[nt][3] * r1;
        if (n1 < Nn) {
            __half2 hh = __floats2half2_rn(c[nt][0], c[nt][1]);
            g_feat1h[n1 * 64 + (col >> 1)] = *(unsigned*)&hh;
        }
        if (n2 < Nn) {
            __half2 hh = __floats2half2_rn(c[nt][2], c[nt][3]);
            g_feat1h[n2 * 64 + (col >> 1)] = *(unsigned*)&hh;
        }
    }
#pragma unroll
    for (int h = 0; h < 8; h++) {
        elp[h] += __shfl_xor_sync(0xffffffffu, elp[h], 1);
        elp[h] += __shfl_xor_sync(0xffffffffu, elp[h], 2);
        erp[h] += __shfl_xor_sync(0xffffffffu, erp[h], 1);
        erp[h] += __shfl_xor_sync(0xffffffffu, erp[h], 2);
    }
    if (n1 < Nn) { g_el1[n1 * 4 + q] = elp[q];     g_er1[n1 * 4 + q] = erp[q]; }
    if (n2 < Nn) { g_el1[n2 * 4 + q] = elp[4 + q]; g_er1[n2 * 4 + q] = erp[4 + q]; }
}

// ---------------- CSR build -------------------------------------------------
__global__ void hist_kernel(const int* __restrict__ dst) {
    int e = blockIdx.x * blockDim.x + threadIdx.x;
    if (e < Ee) atomicAdd(&g_counts[dst[e]], 1);
}

__global__ void scan_block_kernel() {
    __shared__ int sh[256];
    int t = threadIdx.x;
    int i = blockIdx.x * 256 + t;
    int v = (i < Nn) ? g_counts[i] : 0;
    sh[t] = v;
    __syncthreads();
    for (int off = 1; off < 256; off <<= 1) {
        int add = (t >= off) ? sh[t - off] : 0;
        __syncthreads();
        sh[t] += add;
        __syncthreads();
    }
    if (i < Nn) g_offs[i] = sh[t] - v;        // exclusive within block
    if (t == 255) g_bsums[blockIdx.x] = sh[t];
}

__global__ void scan_sums_kernel() {
    __shared__ int sh[512];
    int t = threadIdx.x;
    int v = (t < NB) ? g_bsums[t] : 0;
    sh[t] = v;
    __syncthreads();
    for (int off = 1; off < 512; off <<= 1) {
        int add = (t >= off) ? sh[t - off] : 0;
        __syncthreads();
        sh[t] += add;
        __syncthreads();
    }
    if (t < NB) g_bsums[t] = sh[t] - v;       // exclusive
}

__global__ void scan_add_kernel() {
    int i = blockIdx.x * 256 + threadIdx.x;
    if (i < Nn) {
        int o = g_offs[i] + g_bsums[i >> 8];
        g_offs[i] = o;
        g_cursor[i] = o;
    }
}

__global__ void fill_kernel(const int* __restrict__ src, const int* __restrict__ dst) {
    int e = blockIdx.x * blockDim.x + threadIdx.x;
    if (e < Ee) {
        int s = src[e];
        int p = atomicAdd(&g_cursor[dst[e]], 1);
        g_csr_src[p] = s;
    }
}

// ---------------- agg1: lean gather+softmax+head-mean (warp per dst node) --
__global__ void __launch_bounds__(256) agg1_kernel(const float* __restrict__ b1) {
    int n = (blockIdx.x * blockDim.x + threadIdx.x) >> 5;
    int lane = threadIdx.x & 31;
    if (n >= Nn) return;
    int head = lane >> 3;
    int start = g_offs[n];
    int end = start + g_counts[n];
    float er = g_er1[n * 4 + head];
    float denom = 0.f;
    float4 acc = make_float4(0.f, 0.f, 0.f, 0.f);

#pragma unroll 4
    for (int p = start; p < end; p++) {
        int s = __ldg(&g_csr_src[p]);               // warp-broadcast, L1-resident
        float el = __ldg(&g_el1[s * 4 + head]);
        float ex = __expf(leaky02(el + er));
        denom += ex;
        uint2 raw = __ldcg((const uint2*)&g_feat1h[s * 64 + lane * 2]);  // 256B/warp
        float2 f0 = __half22float2(*(__half2*)&raw.x);
        float2 f1 = __half22float2(*(__half2*)&raw.y);
        acc.x = fmaf(ex, f0.x, acc.x);
        acc.y = fmaf(ex, f0.y, acc.y);
        acc.z = fmaf(ex, f1.x, acc.z);
        acc.w = fmaf(ex, f1.y, acc.w);
    }
    float inv = (denom > 0.f) ? __frcp_rn(denom) : 0.f;
    float4 bv = *(const float4*)&b1[lane * 4];
    float y0 = fmaf(acc.x, inv, bv.x);
    float y1 = fmaf(acc.y, inv, bv.y);
    float y2 = fmaf(acc.z, inv, bv.z);
    float y3 = fmaf(acc.w, inv, bv.w);
    // mean over 4 heads: lanes {L, L^8, L^16, L^24}
    y0 += __shfl_xor_sync(0xffffffffu, y0, 8);
    y1 += __shfl_xor_sync(0xffffffffu, y1, 8);
    y2 += __shfl_xor_sync(0xffffffffu, y2, 8);
    y3 += __shfl_xor_sync(0xffffffffu, y3, 8);
    y0 += __shfl_xor_sync(0xffffffffu, y0, 16);
    y1 += __shfl_xor_sync(0xffffffffu, y1, 16);
    y2 += __shfl_xor_sync(0xffffffffu, y2, 16);
    y3 += __shfl_xor_sync(0xffffffffu, y3, 16);
    if (lane < 8) {
        float4 o = make_float4(fmaxf(0.25f * y0, 0.f), fmaxf(0.25f * y1, 0.f),
                               fmaxf(0.25f * y2, 0.f), fmaxf(0.25f * y3, 0.f));
        *(float4*)&g_h[n * 32 + lane * 4] = o;
    }
}

// ---------------- mid: GEMM2 (32->16) + el2/er2 (warp per node) ------------
__global__ void mid_kernel(const float* __restrict__ W2,
                           const float* __restrict__ al2, const float* __restrict__ ar2) {
    int n = (blockIdx.x * blockDim.x + threadIdx.x) >> 5;
    int lane = threadIdx.x & 31;   // = hidden dim d
    if (n >= Nn) return;
    float hv = g_h[n * 32 + lane];    // coalesced 128B
    float p16[16];
    const float4* wrow = (const float4*)&W2[lane * 16];
#pragma unroll
    for (int q = 0; q < 4; q++) {
        float4 w = __ldg(&wrow[q]);
        p16[q * 4 + 0] = hv * w.x;
        p16[q * 4 + 1] = hv * w.y;
        p16[q * 4 + 2] = hv * w.z;
        p16[q * 4 + 3] = hv * w.w;
    }
#pragma unroll
    for (int o = 1; o <= 16; o <<= 1)
#pragma unroll
        for (int j = 0; j < 16; j++)
            p16[j] += __shfl_xor_sync(0xffffffffu, p16[j], o);
    if (lane < 4) {
        float4 o4 = make_float4(p16[lane * 4], p16[lane * 4 + 1],
                                p16[lane * 4 + 2], p16[lane * 4 + 3]);
        *(float4*)&g_feat2[n * 16 + lane * 4] = o4;
    }
    if (lane == 0) {
        float el2 = 0.f, er2 = 0.f;
#pragma unroll
        for (int j = 0; j < 16; j++) {
            el2 = fmaf(p16[j], __ldg(&al2[j]), el2);
            er2 = fmaf(p16[j], __ldg(&ar2[j]), er2);
        }
        g_el2[n] = el2;
        g_er2[n] = er2;
    }
}

// ---------------- agg2: layer-2 softmax+aggregate (4 lanes per dst node) ---
__global__ void agg2_kernel(const float* __restrict__ b2, float* __restrict__ out) {
    int t = blockIdx.x * blockDim.x + threadIdx.x;
    int n = t >> 2;
    if (n >= Nn) return;
    int c = (t & 3) * 4;
    int start = g_offs[n];
    int end = start + g_counts[n];
    float er = g_er2[n];
    float denom = 0.f;
    float4 acc = make_float4(0.f, 0.f, 0.f, 0.f);
#pragma unroll 4
    for (int p = start; p < end; p++) {
        int s = __ldg(&g_csr_src[p]);
        float ex = __expf(leaky02(__ldg(&g_el2[s]) + er));
        denom += ex;
        float4 f = __ldcg((const float4*)&g_feat2[s * 16 + c]);
        acc.x = fmaf(ex, f.x, acc.x);
        acc.y = fmaf(ex, f.y, acc.y);
        acc.z = fmaf(ex, f.z, acc.z);
        acc.w = fmaf(ex, f.w, acc.w);
    }
    float inv = (denom > 0.f) ? __frcp_rn(denom) : 0.f;
    float4 bv = *(const float4*)&b2[c];
    float4 o4 = make_float4(fmaf(acc.x, inv, bv.x), fmaf(acc.y, inv, bv.y),
                            fmaf(acc.z, inv, bv.z), fmaf(acc.w, inv, bv.w));
    *(float4*)&out[n * 16 + c] = o4;
    // reset counts for the next graph replay (statically zero on first run)
    if ((t & 3) == 0) g_counts[n] = 0;
}

// ---------------- launch ----------------------------------------------------
extern "C" void kernel_launch(void* const* d_in, const int* in_sizes, int n_in,
                              void* d_out, int out_size) {
    const float* x   = (const float*)d_in[0];
    const int*   src = (const int*)d_in[1];
    const int*   dst = (const int*)d_in[2];
    const float* W1  = (const float*)d_in[3];
    const float* al1 = (const float*)d_in[4];
    const float* ar1 = (const float*)d_in[5];
    const float* b1  = (const float*)d_in[6];
    const float* W2  = (const float*)d_in[7];
    const float* al2 = (const float*)d_in[8];
    const float* ar2 = (const float*)d_in[9];
    const float* b2  = (const float*)d_in[10];
    float* out = (float*)d_out;

    // one-time host resources (no device memory; same GPU work every call)
    static cudaStream_t s2 = 0;
    static cudaEvent_t ev_fork = 0, ev_join = 0;
    if (s2 == 0) {
        cudaStreamCreateWithFlags(&s2, cudaStreamNonBlocking);
        cudaEventCreateWithFlags(&ev_fork, cudaEventDisableTiming);
        cudaEventCreateWithFlags(&ev_join, cudaEventDisableTiming);
        cudaFuncSetAttribute(gemm1_kernel,
                             cudaFuncAttributeMaxDynamicSharedMemorySize, SMEM_BYTES);
    }

    // fork: GEMM chain on s2, CSR chain on the capture stream
    cudaEventRecord(ev_fork, 0);
    cudaStreamWaitEvent(s2, ev_fork, 0);

    wconv_kernel<<<64, 256, 0, s2>>>(W1);
    gemm1_kernel<<<GB1, 256, SMEM_BYTES, s2>>>(x, al1, ar1);
    cudaEventRecord(ev_join, s2);

    hist_kernel<<<(Ee + 255) / 256, 256>>>(dst);
    scan_block_kernel<<<NB, 256>>>();
    scan_sums_kernel<<<1, 512>>>();
    scan_add_kernel<<<NB, 256>>>();
    fill_kernel<<<(Ee + 255) / 256, 256>>>(src, dst);

    // join: agg1 needs both fill (stream 0) and gemm1 (s2)
    cudaStreamWaitEvent(0, ev_join, 0);

    agg1_kernel<<<(Nn * 32 + 255) / 256, 256>>>(b1);
    mid_kernel<<<(Nn * 32 + 255) / 256, 256>>>(W2, al2, ar2);
    agg2_kernel<<<(Nn * 4 + 255) / 256, 256>>>(b2, out);
}